// round 17
// baseline (speedup 1.0000x reference)
#include <cuda_runtime.h>
#include <cuda_fp16.h>
#include <cstdint>

#define SQ 2048
#define NBH 32
#define HD 128
#define BM 64            // q rows per CTA (4 warps x 16 rows)
#define BN 64
#define NTHREADS 128
#define PITCH 136        // half elements per V smem row: 128 data + [1, vm, 0..] = 272B
// smem offsets
#define SM_K0 0
#define SM_V0 8192
#define SM_K1 25600
#define SM_V1 33792
#define SM_P0 51200
#define SM_P1 52480
#define SMEM_BYTES 53760
#define SCLF 0.12752836805103852f   // log2(e)/sqrt(128)

// Persistent scratch (no cudaMalloc allowed)
__device__ unsigned g_k8[SQ*NBH*32];   // permuted u8 codes, 128B/row as 32 u32 (kp-interleaved)
__device__ __half g_va[(size_t)SQ*NBH*PITCH]; // augmented dequant V: [vs*code x128, 1, vm, 0 x6]
__device__ float4 g_kpar[SQ*NBH];      // (kscale, kmin, kscale*ksum, -)

// ---------------- prep: K codes -> permuted u8 + params ; V -> augmented dequant fp16 ----------------
// K row word order (kp-interleaved for lds128):
//   word w: kp=w>>4, tg=(w>>2)&3, odd=(w>>1)&1, h=w&1 ; kk=2*kp+odd ; codes k0 = kk*32 + h*16 + tg*4
__global__ void prep_kv(const int* __restrict__ k, const int* __restrict__ v,
                        const float* __restrict__ kmin, const float* __restrict__ kscale,
                        const float* __restrict__ vmin, const float* __restrict__ vscale) {
    int warp = threadIdx.x >> 5, lane = threadIdx.x & 31;
    int row = blockIdx.x * 8 + warp;               // 0 .. S*BH-1
    if (blockIdx.y == 0) {
        // ---- K path ----
        int kk = ((lane >> 4) << 1) + ((lane >> 1) & 1);
        int k0 = kk * 32 + ((lane & 1) << 4) + (((lane >> 2) & 3) << 2);
        int4 c = *(const int4*)(k + (size_t)row * HD + k0);
        unsigned packed = (unsigned)c.x | ((unsigned)c.y << 8) | ((unsigned)c.z << 16) | ((unsigned)c.w << 24);
        g_k8[(size_t)row * 32 + lane] = packed;
        int s = c.x + c.y + c.z + c.w;
        #pragma unroll
        for (int off = 16; off; off >>= 1) s += __shfl_xor_sync(0xffffffffu, s, off);
        if (lane == 0) {
            float ks = kscale[row];
            g_kpar[row] = make_float4(ks, kmin[row], ks * (float)s, 0.f);
        }
    } else {
        // ---- V path ----
        float vs = vscale[row];
        int4 c = *((const int4*)(v + (size_t)row * HD) + lane);
        __half2 p0 = __floats2half2_rn(vs * (float)c.x, vs * (float)c.y);
        __half2 p1 = __floats2half2_rn(vs * (float)c.z, vs * (float)c.w);
        uint2 w; w.x = *(unsigned*)&p0; w.y = *(unsigned*)&p1;
        *((uint2*)(g_va + (size_t)row * PITCH) + lane) = w;
        if (lane == 0) {
            __half ext[8];
            ext[0] = __float2half_rn(1.0f);
            ext[1] = __float2half_rn(vmin[row]);
            #pragma unroll
            for (int i = 2; i < 8; i++) ext[i] = __float2half_rn(0.f);
            *(uint4*)(g_va + (size_t)row * PITCH + 128) = *(uint4*)ext;
        }
    }
}

__device__ __forceinline__ void cp16(uint32_t dst, const void* src) {
    asm volatile("cp.async.cg.shared.global [%0], [%1], 16;" :: "r"(dst), "l"(src));
}
__device__ __forceinline__ uint2 lds64(uint32_t a) {
    uint2 r; asm volatile("ld.shared.v2.u32 {%0,%1}, [%2];" : "=r"(r.x), "=r"(r.y) : "r"(a));
    return r;
}
__device__ __forceinline__ uint4 lds128(uint32_t a) {
    uint4 r; asm volatile("ld.shared.v4.u32 {%0,%1,%2,%3}, [%4];"
                          : "=r"(r.x), "=r"(r.y), "=r"(r.z), "=r"(r.w) : "r"(a));
    return r;
}
__device__ __forceinline__ uint32_t smem_u32(const void* p) {
    uint32_t a;
    asm("{ .reg .u64 t; cvta.to.shared.u64 t, %1; cvt.u32.u64 %0, t; }" : "=r"(a) : "l"(p));
    return a;
}

#define MMAU8(cc, aa, b0v, b1v) \
    asm volatile("mma.sync.aligned.m16n8k32.row.col.s32.u8.u8.s32 " \
        "{%0,%1,%2,%3},{%4,%5,%6,%7},{%8,%9},{%0,%1,%2,%3};" \
        : "+r"(cc[0]), "+r"(cc[1]), "+r"(cc[2]), "+r"(cc[3]) \
        : "r"(aa[0]), "r"(aa[1]), "r"(aa[2]), "r"(aa[3]), "r"(b0v), "r"(b1v))

#define MMA16816(cc, aa, b0v, b1v) \
    asm volatile("mma.sync.aligned.m16n8k16.row.col.f32.f16.f16.f32 " \
        "{%0,%1,%2,%3},{%4,%5,%6,%7},{%8,%9},{%0,%1,%2,%3};" \
        : "+f"(cc[0]), "+f"(cc[1]), "+f"(cc[2]), "+f"(cc[3]) \
        : "r"(aa[0]), "r"(aa[1]), "r"(aa[2]), "r"(aa[3]), "r"(b0v), "r"(b1v))

// ---------------- main: flash attention, u8 QK + fp16 PV with l/b in MMA ----------------
// 4 CTAs/SM: 128 regs forced (65536/(4*128)); smem 4*53760 = 215KB <= 228KB
__global__ __launch_bounds__(NTHREADS, 4) void attn_kernel(
    const int* __restrict__ qcodes,
    const float* __restrict__ qmin, const float* __restrict__ qscale,
    float* __restrict__ out)
{
    extern __shared__ __align__(16) unsigned char smem_raw[];
    const uint32_t sb = smem_u32(smem_raw);

    const int tid = threadIdx.x, warp = tid >> 5, lane = tid & 31;
    const int g = lane >> 2, tg = lane & 3;
    const int bh = blockIdx.y, q0 = blockIdx.x * BM;

    // ---- prologue: pack raw int32 Q codes -> permuted u8 smem (overlays stage-0 K),
    //      row sums + q params -> smem scratch (overlays stage-0 V) ----
    // Q smem layout (prologue-only): kk*2048 + row*32 + [even words: h-interleaved 16B x2]
    {
        const int rowp = tid >> 1, h = tid & 1;    // row 0..63, half h (kk pair 2h,2h+1)
        const int* Qg = qcodes + ((size_t)(q0 + rowp) * NBH + bh) * HD;
        int ssum = 0;
        #pragma unroll
        for (int kki = 0; kki < 2; kki++) {
            int kk = 2 * h + kki;
            unsigned wv[8];
            #pragma unroll
            for (int j = 0; j < 8; j++) {
                int4 c = *(const int4*)(Qg + kk * 32 + j * 4);
                ssum += c.x + c.y + c.z + c.w;
                unsigned packed = (unsigned)c.x | ((unsigned)c.y << 8) |
                                  ((unsigned)c.z << 16) | ((unsigned)c.w << 24);
                wv[(j < 4) ? (2 * j) : (2 * (j - 4) + 1)] = packed;
            }
            *(uint4*)(smem_raw + kk * 2048 + rowp * 32)      = make_uint4(wv[0], wv[1], wv[2], wv[3]);
            *(uint4*)(smem_raw + kk * 2048 + rowp * 32 + 16) = make_uint4(wv[4], wv[5], wv[6], wv[7]);
        }
        int osum = __shfl_xor_sync(0xffffffffu, ssum, 1);
        float qsum = (float)(ssum + osum);
        if (h == 0) {
            size_t gi = (size_t)(q0 + rowp) * NBH + bh;
            float qs = qscale[gi], qm = qmin[gi];
            *(float4*)(smem_raw + SM_V0 + rowp * 16) =
                make_float4(qs * SCLF, (qs * qsum + 128.f * qm) * SCLF, qm * SCLF, 0.f);
        }
    }
    __syncthreads();

    unsigned qf[4][4];
    const int r0 = warp * 16 + g, r1 = r0 + 8;
    #pragma unroll
    for (int kk = 0; kk < 4; kk++) {
        uint2 lo = lds64(sb + (uint32_t)(kk * 2048 + r0 * 32 + tg * 8));
        uint2 hi = lds64(sb + (uint32_t)(kk * 2048 + r1 * 32 + tg * 8));
        qf[kk][0] = lo.x; qf[kk][1] = hi.x; qf[kk][2] = lo.y; qf[kk][3] = hi.y;
    }
    const float4 qp0 = *(const float4*)(smem_raw + SM_V0 + r0 * 16);
    const float4 qp1 = *(const float4*)(smem_raw + SM_V0 + r1 * 16);
    const float qa0 = qp0.x, qB0 = qp0.y, qc0 = qp0.z;
    const float qa1 = qp1.x, qB1 = qp1.y, qc1 = qp1.z;
    __syncthreads();   // done reading Q smem + qpar scratch; stage-0 buffers may be overwritten

    // ---- cp.async tile issue ----
    // K tile smem layout: kp*4096 + n*64 + tg*16  (16B = kk=2kp 8B | kk=2kp+1 8B)
    auto issue_tile = [&](int kb, int st) {
        const int kbase = kb * BN;
        const uint32_t koff = st ? SM_K1 : SM_K0;
        const uint32_t voff = st ? SM_V1 : SM_V0;
        const uint32_t poff = st ? SM_P1 : SM_P0;
        const char* Kg = (const char*)g_k8 + ((size_t)kbase * NBH + bh) * 128;
        const __half* Vg = g_va + ((size_t)kbase * NBH + bh) * PITCH;
        #pragma unroll
        for (int j = 0; j < 4; j++) {
            int c = tid + j * NTHREADS;            // 0..511
            int kp = c >> 8, rem = c & 255;
            int n = rem >> 2, t16 = c & 3;
            cp16(sb + koff + (uint32_t)(kp * 4096 + n * 64 + t16 * 16),
                 Kg + (size_t)n * NBH * 128 + kp * 64 + t16 * 16);
        }
        #pragma unroll
        for (int j = 0; j < 8; j++) {
            int chunk = tid + j * NTHREADS;        // 0..1023 : cols 0..127 (256B/row)
            int row = chunk >> 4, c16 = chunk & 15;
            cp16(sb + voff + (uint32_t)(row * PITCH + c16 * 8) * 2,
                 Vg + (size_t)row * NBH * PITCH + c16 * 8);
        }
        if (tid < 64) {
            // augmented cols 128..135 (16B tail of each row)
            cp16(sb + voff + (uint32_t)(tid * PITCH + 128) * 2,
                 Vg + (size_t)tid * NBH * PITCH + 128);
        } else {
            int key = tid - 64;
            cp16(sb + poff + key * 16, g_kpar + (size_t)(kbase + key) * NBH + bh);
        }
        asm volatile("cp.async.commit_group;" ::: "memory");
    };

    issue_tile(0, 0);

    float o[16][4], ox[4];
    #pragma unroll
    for (int i = 0; i < 16; i++) { o[i][0] = o[i][1] = o[i][2] = o[i][3] = 0.f; }
    ox[0] = ox[1] = ox[2] = ox[3] = 0.f;
    float m0 = -1e30f, m1 = -1e30f;

    for (int kb = 0; kb < SQ / BN; kb++) {
        const int st = kb & 1;
        if (kb + 1 < SQ / BN) {
            issue_tile(kb + 1, st ^ 1);
            asm volatile("cp.async.wait_group 1;" ::: "memory");
        } else {
            asm volatile("cp.async.wait_group 0;" ::: "memory");
        }
        __syncthreads();   // tile kb visible

        const uint32_t koff = st ? SM_K1 : SM_K0;
        const uint32_t voff = st ? SM_V1 : SM_V0;
        const uint32_t poff = st ? SM_P1 : SM_P0;
        const float4* sP4 = (const float4*)(smem_raw + poff);
        const uint32_t sVb = sb + voff;

        // ---- S = Q * K^T in u8 MMA (exact s32); K via lds128, 2 kk per load ----
        int ci[8][4];
        #pragma unroll
        for (int i = 0; i < 8; i++) { ci[i][0] = ci[i][1] = ci[i][2] = ci[i][3] = 0; }
        const uint32_t lbase = sb + koff + (uint32_t)(g * 64 + tg * 16);
        #pragma unroll
        for (int kp = 0; kp < 2; kp++) {
            #pragma unroll
            for (int n8 = 0; n8 < 8; n8++) {
                uint4 b = lds128(lbase + (uint32_t)(kp * 4096 + n8 * 512));
                MMAU8(ci[n8], qf[2*kp],     b.x, b.y);
                MMAU8(ci[n8], qf[2*kp + 1], b.z, b.w);
            }
        }

        // ---- dequant corrections + online softmax ----
        float cf[8][4];
        float mx0 = -1e30f, mx1 = -1e30f;
        #pragma unroll
        for (int n8 = 0; n8 < 8; n8++) {
            int cc = n8 * 8 + 2 * tg;
            float4 Pa = sP4[cc], Pb = sP4[cc + 1];   // (ks, km, ks*ksum, -)
            cf[n8][0] = fmaf(qa0 * Pa.x, (float)ci[n8][0], fmaf(qB0, Pa.y, qc0 * Pa.z));
            cf[n8][1] = fmaf(qa0 * Pb.x, (float)ci[n8][1], fmaf(qB0, Pb.y, qc0 * Pb.z));
            cf[n8][2] = fmaf(qa1 * Pa.x, (float)ci[n8][2], fmaf(qB1, Pa.y, qc1 * Pa.z));
            cf[n8][3] = fmaf(qa1 * Pb.x, (float)ci[n8][3], fmaf(qB1, Pb.y, qc1 * Pb.z));
            mx0 = fmaxf(mx0, fmaxf(cf[n8][0], cf[n8][1]));
            mx1 = fmaxf(mx1, fmaxf(cf[n8][2], cf[n8][3]));
        }
        mx0 = fmaxf(mx0, __shfl_xor_sync(~0u, mx0, 1));
        mx0 = fmaxf(mx0, __shfl_xor_sync(~0u, mx0, 2));
        mx1 = fmaxf(mx1, __shfl_xor_sync(~0u, mx1, 1));
        mx1 = fmaxf(mx1, __shfl_xor_sync(~0u, mx1, 2));
        const float mn0 = fmaxf(m0, mx0), mn1 = fmaxf(m1, mx1);
        const bool nochange = (m0 == mn0) & (m1 == mn1);
        float cr0, cr1;
        asm("ex2.approx.f32 %0, %1;" : "=f"(cr0) : "f"(m0 - mn0));
        asm("ex2.approx.f32 %0, %1;" : "=f"(cr1) : "f"(m1 - mn1));
        m0 = mn0; m1 = mn1;

        // ---- p = 2^(S - m) in fp16 pairs (MUFU f16x2); becomes PV A operand directly ----
        #pragma unroll
        for (int n8 = 0; n8 < 8; n8++) {
            __half2 x0 = __floats2half2_rn(cf[n8][0] - mn0, cf[n8][1] - mn0);
            __half2 x1 = __floats2half2_rn(cf[n8][2] - mn1, cf[n8][3] - mn1);
            __half2 p0 = h2exp2(x0);
            __half2 p1 = h2exp2(x1);
            ci[n8][0] = (int)*(unsigned*)&p0;   // rows r0, keys cc..cc+1
            ci[n8][1] = (int)*(unsigned*)&p1;   // rows r1
        }
        if (!__all_sync(0xffffffffu, nochange)) {
            #pragma unroll
            for (int i = 0; i < 16; i++) {
                o[i][0] *= cr0; o[i][1] *= cr0; o[i][2] *= cr1; o[i][3] *= cr1;
            }
            ox[0] *= cr0; ox[1] *= cr0; ox[2] *= cr1; ox[3] *= cr1;
        }

        // ---- O += p * Vaug  (fp16 MMA; V via ldmatrix.trans; cols 128/129 = l/b) ----
        #pragma unroll
        for (int kk = 0; kk < 4; kk++) {
            unsigned a[4] = { (unsigned)ci[2*kk][0], (unsigned)ci[2*kk][1],
                              (unsigned)ci[2*kk + 1][0], (unsigned)ci[2*kk + 1][1] };
            #pragma unroll
            for (int nb = 0; nb < 8; nb++) {
                int rowl = kk * 16 + (lane & 15);
                int col  = nb * 16 + ((lane & 16) ? 8 : 0);
                unsigned addr = sVb + ((unsigned)(rowl * PITCH + col) << 1);
                unsigned v0, v1, v2, v3;
                asm volatile("ldmatrix.sync.aligned.m8n8.x4.trans.shared.b16 {%0,%1,%2,%3}, [%4];"
                             : "=r"(v0), "=r"(v1), "=r"(v2), "=r"(v3) : "r"(addr));
                MMA16816(o[2*nb],     a, v0, v1);
                MMA16816(o[2*nb + 1], a, v2, v3);
            }
            {   // extra n8 block: cols 128..135 (l, b, zeros)
                int rowl = kk * 16 + (lane & 15);
                unsigned addr = sVb + ((unsigned)(rowl * PITCH + 128) << 1);
                unsigned v0, v1;
                asm volatile("ldmatrix.sync.aligned.m8n8.x2.trans.shared.b16 {%0,%1}, [%2];"
                             : "=r"(v0), "=r"(v1) : "r"(addr));
                MMA16816(ox, a, v0, v1);
            }
        }
        __syncthreads();   // all reads of this stage done before refill
    }

    // ---- epilogue: l/b from MMA cols 128/129 (tg==0 lane), normalize, store fp32 ----
    const int qlead = lane & 28;
    const float l0 = __shfl_sync(0xffffffffu, ox[0], qlead);
    const float b0 = __shfl_sync(0xffffffffu, ox[1], qlead);
    const float l1 = __shfl_sync(0xffffffffu, ox[2], qlead);
    const float b1 = __shfl_sync(0xffffffffu, ox[3], qlead);
    const float iv0 = 1.f / l0, iv1 = 1.f / l1;
    float* O0 = out + (size_t)(q0 + r0) * NBH * HD + (size_t)bh * HD;
    float* O1 = out + (size_t)(q0 + r1) * NBH * HD + (size_t)bh * HD;
    #pragma unroll
    for (int i = 0; i < 16; i++) {
        int d0 = i * 8 + 2 * tg;
        float2 w0 = make_float2((o[i][0] + b0) * iv0, (o[i][1] + b0) * iv0);
        float2 w1 = make_float2((o[i][2] + b1) * iv1, (o[i][3] + b1) * iv1);
        *(float2*)(O0 + d0) = w0;
        *(float2*)(O1 + d0) = w1;
    }
}

extern "C" void kernel_launch(void* const* d_in, const int* in_sizes, int n_in,
                              void* d_out, int out_size) {
    const int*   q   = (const int*)d_in[0];
    const int*   k   = (const int*)d_in[1];
    const int*   v   = (const int*)d_in[2];
    const float* qmn = (const float*)d_in[3];
    const float* qsc = (const float*)d_in[4];
    const float* kmn = (const float*)d_in[5];
    const float* ksc = (const float*)d_in[6];
    const float* vmn = (const float*)d_in[7];
    const float* vsc = (const float*)d_in[8];

    (void)cudaFuncSetAttribute(attn_kernel, cudaFuncAttributeMaxDynamicSharedMemorySize, SMEM_BYTES);

    dim3 pg(SQ * NBH / 8, 2);   // y=0: K pack+params, y=1: V dequant+augment
    prep_kv<<<pg, 256>>>(k, v, kmn, ksc, vmn, vsc);

    dim3 ag(SQ / BM, NBH);   // qtile fastest -> concurrent CTAs share a head's K/V in L2
    attn_kernel<<<ag, NTHREADS, SMEM_BYTES>>>(q, qmn, qsc, (float*)d_out);
}